// round 2
// baseline (speedup 1.0000x reference)
#include <cuda_runtime.h>
#include <math.h>
#include <stdint.h>

// ---------------------------------------------------------------------------
// Problem constants
// ---------------------------------------------------------------------------
#define GQ      32
#define NT_MAX  32768
#define E_TOT   524288
#define HF      128
#define EPSB    1e-5f

// per-layer: ntin {32768,26240,20992,16800}  n {1024,820,656,525}  k {820,656,525,420}

// ---------------------------------------------------------------------------
// Device scratch
// ---------------------------------------------------------------------------
__device__ float g_h0[NT_MAX * HF];
__device__ float g_h1[NT_MAX * HF];
__device__ float g_agg[NT_MAX * HF];
__device__ float g_score[NT_MAX];
__device__ int   g_perm[NT_MAX];
__device__ int   g_map[NT_MAX];
__device__ int   g_src[E_TOT];
__device__ int   g_dst[E_TOT];
__device__ int   g_csr[E_TOT];
__device__ int   g_deg[NT_MAX];
__device__ int   g_rowptr[NT_MAX + 1];
__device__ int   g_cursor[NT_MAX];
__device__ float g_colsum[HF];
__device__ float g_colsq[HF];
__device__ float g_scale[HF];
__device__ float g_shift[HF];
__device__ float g_invp[1];
__device__ float g_flat[GQ * 1024];
__device__ float g_hd[GQ * 512];

// ---------------------------------------------------------------------------
// Edge init / CSR build
// ---------------------------------------------------------------------------
__global__ void init_edges_k(const int* __restrict__ ei,
                             int* __restrict__ src, int* __restrict__ dst)
{
    int e = blockIdx.x * blockDim.x + threadIdx.x;
    if (e >= E_TOT) return;
    src[e] = ei[e];
    dst[e] = ei[E_TOT + e];
}

__global__ void deg_count_k(const int* __restrict__ src, const int* __restrict__ dst,
                            int* __restrict__ deg)
{
    int e = blockIdx.x * blockDim.x + threadIdx.x;
    if (e >= E_TOT) return;
    int s = src[e];
    if (s >= 0) atomicAdd(&deg[dst[e]], 1);
}

// single-block exclusive scan over deg[0..nt) -> rowptr, cursor; zeros BN accumulators
__global__ __launch_bounds__(1024) void scan_k(const int* __restrict__ deg, int nt,
                                               int* __restrict__ rowptr, int* __restrict__ cursor,
                                               float* __restrict__ colsum, float* __restrict__ colsq)
{
    __shared__ int part[1024];
    int t = threadIdx.x;
    int base = t * 32;
    int s = 0;
    for (int i = 0; i < 32; i++) {
        int idx = base + i;
        s += (idx < nt) ? deg[idx] : 0;
    }
    part[t] = s;
    __syncthreads();
    for (int off = 1; off < 1024; off <<= 1) {
        int v = (t >= off) ? part[t - off] : 0;
        __syncthreads();
        part[t] += v;
        __syncthreads();
    }
    int run = part[t] - s;     // exclusive prefix of this thread's chunk
    for (int i = 0; i < 32; i++) {
        int idx = base + i;
        if (idx < nt) {
            rowptr[idx] = run;
            cursor[idx] = run;
            run += deg[idx];
        }
    }
    if (t == 1023) rowptr[nt] = part[1023];
    if (t < HF) { colsum[t] = 0.f; colsq[t] = 0.f; }
}

__global__ void fill_k(const int* __restrict__ src, const int* __restrict__ dst,
                       int* __restrict__ cursor, int* __restrict__ csr)
{
    int e = blockIdx.x * blockDim.x + threadIdx.x;
    if (e >= E_TOT) return;
    int s = src[e];
    if (s < 0) return;
    int slot = atomicAdd(&cursor[dst[e]], 1);
    csr[slot] = s;
}

// one warp per node: agg[node] = mean of h[src] over incident edges
__global__ void gather_k(const float* __restrict__ h,
                         const int* __restrict__ rowptr, const int* __restrict__ csr,
                         float* __restrict__ agg, int nt)
{
    int w = (blockIdx.x * blockDim.x + threadIdx.x) >> 5;
    int lane = threadIdx.x & 31;
    if (w >= nt) return;
    int b = rowptr[w], e = rowptr[w + 1];
    const float4* h4 = (const float4*)h;
    float4 acc = make_float4(0.f, 0.f, 0.f, 0.f);
    int i = b;
    if (i < e) {
        int s = csr[i];
        for (++i; i < e; ++i) {
            int sn = csr[i];
            float4 v = __ldg(&h4[(size_t)s * 32 + lane]);
            acc.x += v.x; acc.y += v.y; acc.z += v.z; acc.w += v.w;
            s = sn;
        }
        float4 v = __ldg(&h4[(size_t)s * 32 + lane]);
        acc.x += v.x; acc.y += v.y; acc.z += v.z; acc.w += v.w;
    }
    float rc = 1.0f / fmaxf((float)(e - b), 1.0f);
    acc.x *= rc; acc.y *= rc; acc.z *= rc; acc.w *= rc;
    ((float4*)agg)[(size_t)w * 32 + lane] = acc;
}

// ---------------------------------------------------------------------------
// GEMM: C[M,128] = A1(Mx128)@B1 + A2(Mx128)@B2 + bias
// Block tile 256x128, 8 warps (4x2), warp tile 64x64, lanes 8x4, thread 8x16.
// Double-buffered smem, BK=8.
// ---------------------------------------------------------------------------
__global__ __launch_bounds__(256) void gemm2_k(
    const float* __restrict__ A1, const float* __restrict__ A2,
    const float* __restrict__ B1, const float* __restrict__ B2,
    const float* __restrict__ bias, float* __restrict__ C, int M)
{
    __shared__ float As[2][8][260];   // [k][m], padded rows (260 % 4 == 0, stride breaks conflicts)
    __shared__ float Bs[2][8][128];   // [k][n]

    const int t = threadIdx.x;
    const int wid = t >> 5, lane = t & 31;
    const int warpM = wid & 3, warpN = wid >> 2;
    const int lm = lane >> 2, ln = lane & 3;
    const int row0 = blockIdx.x * 256;
    const int aoff = warpM * 64 + lm * 8;
    const int boff = warpN * 64 + ln * 16;
    const int grow = row0 + t;
    const int bkr = t >> 5;          // B stage: k row
    const int bcol = (t & 31) * 4;   // B stage: col

    float acc[8][16];
#pragma unroll
    for (int i = 0; i < 8; i++)
#pragma unroll
        for (int j = 0; j < 16; j++) acc[i][j] = 0.f;

    float4 a0, a1, b0;
    // load tile 0 (A1/B1, kb=0)
    if (grow < M) {
        const float4* p = (const float4*)(A1 + (size_t)grow * 128);
        a0 = p[0]; a1 = p[1];
    } else {
        a0 = make_float4(0.f, 0.f, 0.f, 0.f); a1 = a0;
    }
    b0 = *(const float4*)(B1 + (size_t)bkr * 128 + bcol);
    {
        float av[8] = {a0.x, a0.y, a0.z, a0.w, a1.x, a1.y, a1.z, a1.w};
#pragma unroll
        for (int kk = 0; kk < 8; kk++) As[0][kk][t] = av[kk];
        *(float4*)&Bs[0][bkr][bcol] = b0;
    }
    __syncthreads();

    int cur = 0;
#pragma unroll 1
    for (int kt = 0; kt < 32; kt++) {
        if (kt < 31) {
            int nk = kt + 1;
            const float* Asrc = (nk < 16) ? A1 : A2;
            const float* Bsrc = (nk < 16) ? B1 : B2;
            int kb = (nk & 15) * 8;
            if (grow < M) {
                const float4* p = (const float4*)(Asrc + (size_t)grow * 128 + kb);
                a0 = p[0]; a1 = p[1];
            } else {
                a0 = make_float4(0.f, 0.f, 0.f, 0.f); a1 = a0;
            }
            b0 = *(const float4*)(Bsrc + (size_t)(kb + bkr) * 128 + bcol);
        }
#pragma unroll
        for (int k = 0; k < 8; k++) {
            float a[8], b[16];
            *(float4*)&a[0] = *(float4*)&As[cur][k][aoff];
            *(float4*)&a[4] = *(float4*)&As[cur][k][aoff + 4];
            *(float4*)&b[0]  = *(float4*)&Bs[cur][k][boff];
            *(float4*)&b[4]  = *(float4*)&Bs[cur][k][boff + 4];
            *(float4*)&b[8]  = *(float4*)&Bs[cur][k][boff + 8];
            *(float4*)&b[12] = *(float4*)&Bs[cur][k][boff + 12];
#pragma unroll
            for (int i = 0; i < 8; i++)
#pragma unroll
                for (int j = 0; j < 16; j++)
                    acc[i][j] += a[i] * b[j];
        }
        if (kt < 31) {
            int nb = cur ^ 1;
            float av[8] = {a0.x, a0.y, a0.z, a0.w, a1.x, a1.y, a1.z, a1.w};
#pragma unroll
            for (int kk = 0; kk < 8; kk++) As[nb][kk][t] = av[kk];
            *(float4*)&Bs[nb][bkr][bcol] = b0;
            __syncthreads();
            cur = nb;
        }
    }

    float bc[16];
#pragma unroll
    for (int j = 0; j < 16; j++) bc[j] = __ldg(bias + boff + j);
#pragma unroll
    for (int i = 0; i < 8; i++) {
        int row = row0 + warpM * 64 + lm * 8 + i;
        if (row < M) {
#pragma unroll
            for (int j4 = 0; j4 < 4; j4++) {
                float4 o;
                o.x = acc[i][j4 * 4 + 0] + bc[j4 * 4 + 0];
                o.y = acc[i][j4 * 4 + 1] + bc[j4 * 4 + 1];
                o.z = acc[i][j4 * 4 + 2] + bc[j4 * 4 + 2];
                o.w = acc[i][j4 * 4 + 3] + bc[j4 * 4 + 3];
                *(float4*)(C + (size_t)row * 128 + boff + j4 * 4) = o;
            }
        }
    }
}

// ---------------------------------------------------------------------------
// BN / score / topk / pool
// ---------------------------------------------------------------------------
__global__ void bn_partial_k(const float* __restrict__ h, int M,
                             float* __restrict__ colsum, float* __restrict__ colsq)
{
    int f = threadIdx.x;
    int r0 = blockIdx.x * 256;
    int r1 = min(r0 + 256, M);
    float s = 0.f, q = 0.f;
    for (int r = r0; r < r1; r++) {
        float v = h[(size_t)r * HF + f];
        s += v; q += v * v;
    }
    atomicAdd(&colsum[f], s);
    atomicAdd(&colsq[f], q);
}

__global__ void bn_finalize_k(const float* __restrict__ colsum, const float* __restrict__ colsq,
                              float invM,
                              const float* __restrict__ g, const float* __restrict__ be,
                              const float* __restrict__ p,
                              float* __restrict__ scale, float* __restrict__ shift,
                              float* __restrict__ invp)
{
    __shared__ float red[128];
    int f = threadIdx.x;
    float mu = colsum[f] * invM;
    float var = colsq[f] * invM - mu * mu;
    float rstd = rsqrtf(var + EPSB);
    float sc = rstd * g[f];
    scale[f] = sc;
    shift[f] = be[f] - mu * sc;
    float pv = p[f];
    red[f] = pv * pv;
    __syncthreads();
    for (int o = 64; o > 0; o >>= 1) {
        if (f < o) red[f] += red[f + o];
        __syncthreads();
    }
    if (f == 0) invp[0] = rsqrtf(red[0]);
}

__global__ void bn_relu_score_k(float* __restrict__ h, int M,
                                const float* __restrict__ scale, const float* __restrict__ shift,
                                const float* __restrict__ p, const float* __restrict__ invp,
                                float* __restrict__ score)
{
    int w = (blockIdx.x * blockDim.x + threadIdx.x) >> 5;
    int lane = threadIdx.x & 31;
    if (w >= M) return;
    float4* row = (float4*)(h + (size_t)w * HF);
    float4 v = row[lane];
    float4 sc = ((const float4*)scale)[lane];
    float4 sh = ((const float4*)shift)[lane];
    float4 pv = ((const float4*)p)[lane];
    v.x = fmaxf(v.x * sc.x + sh.x, 0.f);
    v.y = fmaxf(v.y * sc.y + sh.y, 0.f);
    v.z = fmaxf(v.z * sc.z + sh.z, 0.f);
    v.w = fmaxf(v.w * sc.w + sh.w, 0.f);
    row[lane] = v;
    float acc = v.x * pv.x + v.y * pv.y + v.z * pv.z + v.w * pv.w;
#pragma unroll
    for (int o = 16; o > 0; o >>= 1) acc += __shfl_xor_sync(0xffffffffu, acc, o);
    if (lane == 0) score[w] = acc * invp[0];
}

__global__ __launch_bounds__(1024) void topk_k(const float* __restrict__ score,
                                               int n, int k,
                                               int* __restrict__ map, int* __restrict__ perm)
{
    __shared__ float s[1024];
    __shared__ int id[1024];
    int g = blockIdx.x, t = threadIdx.x;
    s[t] = (t < n) ? score[g * n + t] : __int_as_float(0xff800000u);
    id[t] = t;
    __syncthreads();
    for (int size = 2; size <= 1024; size <<= 1) {
        for (int stride = size >> 1; stride > 0; stride >>= 1) {
            int pos = t ^ stride;
            if (pos > t) {
                bool desc = ((t & size) == 0);
                float s1 = s[t], s2 = s[pos];
                if (desc ? (s1 < s2) : (s1 > s2)) {
                    s[t] = s2; s[pos] = s1;
                    int tmp = id[t]; id[t] = id[pos]; id[pos] = tmp;
                }
            }
            __syncthreads();
        }
    }
    if (t < k) {
        int oldg = g * n + id[t];
        int newg = g * k + t;
        map[oldg] = newg;
        perm[newg] = oldg;
    }
}

__global__ void gather_gate_k(const float* __restrict__ h, const int* __restrict__ perm,
                              const float* __restrict__ score, float* __restrict__ out, int Mout)
{
    int w = (blockIdx.x * blockDim.x + threadIdx.x) >> 5;
    int lane = threadIdx.x & 31;
    if (w >= Mout) return;
    int old = perm[w];
    float gate = tanhf(score[old]);
    float4 v = ((const float4*)h)[(size_t)old * 32 + lane];
    v.x *= gate; v.y *= gate; v.z *= gate; v.w *= gate;
    ((float4*)out)[(size_t)w * 32 + lane] = v;
}

__global__ void readout_k(const float* __restrict__ hp, int k,
                          float* __restrict__ flat, int off)
{
    int g = blockIdx.x, f = threadIdx.x; // 128 threads
    const float* base = hp + ((size_t)g * k) * HF + f;
    float s = 0.f, m = __int_as_float(0xff800000u);
    for (int r = 0; r < k; r++) {
        float v = base[(size_t)r * HF];
        s += v;
        m = fmaxf(m, v);
    }
    flat[g * 1024 + off + f] = s;
    flat[g * 1024 + off + 128 + f] = m;
}

__global__ void remap_edges_k(int* __restrict__ src, int* __restrict__ dst,
                              const int* __restrict__ map)
{
    int e = blockIdx.x * blockDim.x + threadIdx.x;
    if (e >= E_TOT) return;
    int s = src[e];
    if (s < 0) return;
    int ns = map[s];
    int nd = map[dst[e]];
    if ((ns | nd) < 0) {
        src[e] = -1;
    } else {
        src[e] = ns;
        dst[e] = nd;
    }
}

// ---------------------------------------------------------------------------
// Final MLP
// ---------------------------------------------------------------------------
__global__ __launch_bounds__(512) void dense1_k(const float* __restrict__ flat,
                                                const float* __restrict__ Wd1,
                                                const float* __restrict__ bd1,
                                                float* __restrict__ hd)
{
    __shared__ float fr[1024];
    int g = blockIdx.x, t = threadIdx.x;
    fr[t] = flat[g * 1024 + t];
    fr[t + 512] = flat[g * 1024 + t + 512];
    __syncthreads();
    float acc = bd1[t];
    for (int kk = 0; kk < 1024; kk++)
        acc += fr[kk] * Wd1[(size_t)kk * 512 + t];
    hd[g * 512 + t] = fmaxf(acc, 0.f);
}

__global__ __launch_bounds__(512) void dense2_k(const float* __restrict__ hd,
                                                const float* __restrict__ Wd2,
                                                const float* __restrict__ bd2,
                                                float* __restrict__ out)
{
    __shared__ float hr[512];
    int g = blockIdx.x, t = threadIdx.x;
    hr[t] = hd[g * 512 + t];
    __syncthreads();
    if (t < 320) {
        int c = t >> 5, lane = t & 31;
        float acc = 0.f;
        for (int kk = lane; kk < 512; kk += 32)
            acc += hr[kk] * Wd2[(size_t)kk * 10 + c];
#pragma unroll
        for (int o = 16; o > 0; o >>= 1) acc += __shfl_down_sync(0xffffffffu, acc, o);
        if (lane == 0) out[g * 10 + c] = acc + bd2[c];
    }
}

// ---------------------------------------------------------------------------
// Host driver
// ---------------------------------------------------------------------------
extern "C" void kernel_launch(void* const* d_in, const int* in_sizes, int n_in,
                              void* d_out, int out_size)
{
    (void)in_sizes; (void)n_in; (void)out_size;

    const float* x  = (const float*)d_in[0];
    const int*   ei = (const int*)d_in[1];
    const float *Wl[4], *Wr[4], *bb[4], *gg[4], *be[4], *pp[4];
    for (int l = 0; l < 4; l++) {
        int b = 3 + 6 * l;
        Wl[l] = (const float*)d_in[b + 0];
        Wr[l] = (const float*)d_in[b + 1];
        bb[l] = (const float*)d_in[b + 2];
        gg[l] = (const float*)d_in[b + 3];
        be[l] = (const float*)d_in[b + 4];
        pp[l] = (const float*)d_in[b + 5];
    }
    const float* Wd1 = (const float*)d_in[27];
    const float* bd1 = (const float*)d_in[28];
    const float* Wd2 = (const float*)d_in[29];
    const float* bd2 = (const float*)d_in[30];
    float* out = (float*)d_out;

    float *h0, *h1, *agg, *score, *colsum, *colsq, *scale, *shift, *invp, *flat, *hd;
    int *src, *dst, *csr, *deg, *rowptr, *cursor, *perm, *map;
    cudaGetSymbolAddress((void**)&h0, g_h0);
    cudaGetSymbolAddress((void**)&h1, g_h1);
    cudaGetSymbolAddress((void**)&agg, g_agg);
    cudaGetSymbolAddress((void**)&score, g_score);
    cudaGetSymbolAddress((void**)&colsum, g_colsum);
    cudaGetSymbolAddress((void**)&colsq, g_colsq);
    cudaGetSymbolAddress((void**)&scale, g_scale);
    cudaGetSymbolAddress((void**)&shift, g_shift);
    cudaGetSymbolAddress((void**)&invp, g_invp);
    cudaGetSymbolAddress((void**)&flat, g_flat);
    cudaGetSymbolAddress((void**)&hd, g_hd);
    cudaGetSymbolAddress((void**)&src, g_src);
    cudaGetSymbolAddress((void**)&dst, g_dst);
    cudaGetSymbolAddress((void**)&csr, g_csr);
    cudaGetSymbolAddress((void**)&deg, g_deg);
    cudaGetSymbolAddress((void**)&rowptr, g_rowptr);
    cudaGetSymbolAddress((void**)&cursor, g_cursor);
    cudaGetSymbolAddress((void**)&perm, g_perm);
    cudaGetSymbolAddress((void**)&map, g_map);

    init_edges_k<<<E_TOT / 256, 256>>>(ei, src, dst);

    const int ntin_a[4] = {32768, 26240, 20992, 16800};
    const int n_a[4]    = {1024, 820, 656, 525};
    const int k_a[4]    = {820, 656, 525, 420};

    const float* hin = x;
    for (int l = 0; l < 4; l++) {
        int M = ntin_a[l];
        int n = n_a[l];
        int kk = k_a[l];
        int Mout = GQ * kk;

        // CSR build + gather (mean)
        cudaMemsetAsync(deg, 0, (size_t)M * sizeof(int));
        deg_count_k<<<E_TOT / 256, 256>>>(src, dst, deg);
        scan_k<<<1, 1024>>>(deg, M, rowptr, cursor, colsum, colsq);
        fill_k<<<E_TOT / 256, 256>>>(src, dst, cursor, csr);
        gather_k<<<(M + 7) / 8, 256>>>(hin, rowptr, csr, agg, M);

        // h = mean@Wl + hin@Wr + bb
        gemm2_k<<<(M + 255) / 256, 256>>>(agg, hin, Wl[l], Wr[l], bb[l], h1, M);

        // BatchNorm + ReLU + score
        bn_partial_k<<<(M + 255) / 256, 128>>>(h1, M, colsum, colsq);
        bn_finalize_k<<<1, 128>>>(colsum, colsq, 1.0f / (float)M,
                                  gg[l], be[l], pp[l], scale, shift, invp);
        bn_relu_score_k<<<(M + 7) / 8, 256>>>(h1, M, scale, shift, pp[l], invp, score);

        // TopK pooling
        cudaMemsetAsync(map, 0xFF, (size_t)M * sizeof(int));
        topk_k<<<GQ, 1024>>>(score, n, kk, map, perm);
        gather_gate_k<<<(Mout + 7) / 8, 256>>>(h1, perm, score, h0, Mout);
        readout_k<<<GQ, 128>>>(h0, kk, flat, l * 256);
        if (l < 3) remap_edges_k<<<E_TOT / 256, 256>>>(src, dst, map);

        hin = h0;
    }

    dense1_k<<<GQ, 512>>>(flat, Wd1, bd1, hd);
    dense2_k<<<GQ, 512>>>(hd, Wd2, bd2, out);
}

// round 3
// speedup vs baseline: 1.1947x; 1.1947x over previous
#include <cuda_runtime.h>
#include <math.h>
#include <stdint.h>

// ---------------------------------------------------------------------------
// Problem constants
// ---------------------------------------------------------------------------
#define GQ      32
#define NT_MAX  32768
#define E_TOT   524288
#define HF      128
#define EPSB    1e-5f

// per-layer: ntin {32768,26240,20992,16800}  n {1024,820,656,525}  k {820,656,525,420}

// ---------------------------------------------------------------------------
// Device scratch
// ---------------------------------------------------------------------------
__device__ float g_h0[NT_MAX * HF];
__device__ float g_h1[NT_MAX * HF];
__device__ float g_agg[NT_MAX * HF];
__device__ float g_cnt[NT_MAX];
__device__ float g_score[NT_MAX];
__device__ int   g_perm[NT_MAX];
__device__ int   g_map[NT_MAX];
__device__ int   g_src[E_TOT];
__device__ int   g_dst[E_TOT];
__device__ float g_colsum[HF];
__device__ float g_colsq[HF];
__device__ float g_scale[HF];
__device__ float g_shift[HF];
__device__ float g_invp[1];
__device__ float g_flat[GQ * 1024];
__device__ float g_hd[GQ * 512];

// ---------------------------------------------------------------------------
// Vector global reduction (sm_90+): one instruction adds 4 floats
// ---------------------------------------------------------------------------
__device__ __forceinline__ void red_add_v4(float* addr, float4 v)
{
    asm volatile("red.global.add.v4.f32 [%0], {%1,%2,%3,%4};"
                 :: "l"(addr), "f"(v.x), "f"(v.y), "f"(v.z), "f"(v.w)
                 : "memory");
}

// ---------------------------------------------------------------------------
// Edge init
// ---------------------------------------------------------------------------
__global__ void init_edges_k(const int* __restrict__ ei,
                             int* __restrict__ src, int* __restrict__ dst)
{
    int e = blockIdx.x * blockDim.x + threadIdx.x;
    if (e >= E_TOT) return;
    src[e] = ei[e];
    dst[e] = ei[E_TOT + e];
}

// one warp per edge; one v4 reduction per lane
__global__ void scatter_agg_k(const float* __restrict__ h,
                              const int* __restrict__ src, const int* __restrict__ dst,
                              float* __restrict__ agg, float* __restrict__ cnt)
{
    int w = (blockIdx.x * blockDim.x + threadIdx.x) >> 5;
    int lane = threadIdx.x & 31;
    if (w >= E_TOT) return;
    int s = __ldg(src + w);
    if (s < 0) return;                 // invalid edge
    int d = __ldg(dst + w);
    float4 v = __ldg(((const float4*)h) + (size_t)s * 32 + lane);
    red_add_v4(agg + (size_t)d * HF + lane * 4, v);
    if (lane == 0) atomicAdd(cnt + d, 1.0f);
}

__global__ void mean_div_k(float* __restrict__ agg, const float* __restrict__ cnt, int total4)
{
    int i = blockIdx.x * blockDim.x + threadIdx.x;  // over float4 elements
    if (i >= total4) return;
    float c = cnt[i >> 5];
    float rc = 1.0f / fmaxf(c, 1.0f);
    float4 v = ((float4*)agg)[i];
    v.x *= rc; v.y *= rc; v.z *= rc; v.w *= rc;
    ((float4*)agg)[i] = v;
}

// ---------------------------------------------------------------------------
// GEMM: C[M,128] = A1(Mx128)@B1 + A2(Mx128)@B2 + bias   (proven R1 kernel)
// ---------------------------------------------------------------------------
__global__ __launch_bounds__(256) void gemm_dual_k(
    const float* __restrict__ A1, const float* __restrict__ A2,
    const float* __restrict__ B1, const float* __restrict__ B2,
    const float* __restrict__ bias, float* __restrict__ C, int M)
{
    __shared__ __align__(16) float As[16][128];
    __shared__ __align__(16) float Bs[16][128];
    const int tid = threadIdx.x;
    const int tx = tid & 15;     // col*8
    const int ty = tid >> 4;     // row*8
    const int row0 = blockIdx.x * 128;

    float acc[8][8];
#pragma unroll
    for (int i = 0; i < 8; i++)
#pragma unroll
        for (int j = 0; j < 8; j++) acc[i][j] = 0.0f;

    for (int k0 = 0; k0 < 256; k0 += 16) {
        const float* Asrc = (k0 < 128) ? A1 : A2;
        const float* Bsrc = (k0 < 128) ? B1 : B2;
        const int kbase = (k0 < 128) ? k0 : (k0 - 128);
#pragma unroll
        for (int i = 0; i < 2; i++) {
            int task = tid + i * 256;           // 0..511
            int r = task >> 2;                  // 0..127
            int kq = (task & 3) << 2;           // 0,4,8,12
            float4 v = make_float4(0.f, 0.f, 0.f, 0.f);
            int grow = row0 + r;
            if (grow < M)
                v = *(const float4*)(Asrc + (size_t)grow * 128 + kbase + kq);
            As[kq + 0][r] = v.x; As[kq + 1][r] = v.y;
            As[kq + 2][r] = v.z; As[kq + 3][r] = v.w;
        }
#pragma unroll
        for (int i = 0; i < 2; i++) {
            int task = tid + i * 256;
            int kr = task >> 5;                 // 0..15
            int nc = (task & 31) << 2;          // 0..124
            *(float4*)&Bs[kr][nc] =
                *(const float4*)(Bsrc + (size_t)(kbase + kr) * 128 + nc);
        }
        __syncthreads();
#pragma unroll
        for (int k = 0; k < 16; k++) {
            float a[8], b[8];
            *(float4*)&a[0] = *(float4*)&As[k][ty * 8];
            *(float4*)&a[4] = *(float4*)&As[k][ty * 8 + 4];
            *(float4*)&b[0] = *(float4*)&Bs[k][tx * 8];
            *(float4*)&b[4] = *(float4*)&Bs[k][tx * 8 + 4];
#pragma unroll
            for (int i = 0; i < 8; i++)
#pragma unroll
                for (int j = 0; j < 8; j++)
                    acc[i][j] += a[i] * b[j];
        }
        __syncthreads();
    }

    float bcol[8];
#pragma unroll
    for (int j = 0; j < 8; j++) bcol[j] = bias[tx * 8 + j];
#pragma unroll
    for (int i = 0; i < 8; i++) {
        int r = row0 + ty * 8 + i;
        if (r < M) {
            float4 o0 = make_float4(acc[i][0] + bcol[0], acc[i][1] + bcol[1],
                                    acc[i][2] + bcol[2], acc[i][3] + bcol[3]);
            float4 o1 = make_float4(acc[i][4] + bcol[4], acc[i][5] + bcol[5],
                                    acc[i][6] + bcol[6], acc[i][7] + bcol[7]);
            *(float4*)(C + (size_t)r * 128 + tx * 8) = o0;
            *(float4*)(C + (size_t)r * 128 + tx * 8 + 4) = o1;
        }
    }
}

// ---------------------------------------------------------------------------
// BN / score / topk / pool
// ---------------------------------------------------------------------------
__global__ void bn_partial_k(const float* __restrict__ h, int M,
                             float* __restrict__ colsum, float* __restrict__ colsq)
{
    int f = threadIdx.x;
    int r0 = blockIdx.x * 256;
    int r1 = min(r0 + 256, M);
    float s = 0.f, q = 0.f;
    for (int r = r0; r < r1; r++) {
        float v = h[(size_t)r * HF + f];
        s += v; q += v * v;
    }
    atomicAdd(&colsum[f], s);
    atomicAdd(&colsq[f], q);
}

__global__ void bn_finalize_k(const float* __restrict__ colsum, const float* __restrict__ colsq,
                              float invM,
                              const float* __restrict__ g, const float* __restrict__ be,
                              const float* __restrict__ p,
                              float* __restrict__ scale, float* __restrict__ shift,
                              float* __restrict__ invp)
{
    __shared__ float red[128];
    int f = threadIdx.x;
    float mu = colsum[f] * invM;
    float var = colsq[f] * invM - mu * mu;
    float rstd = rsqrtf(var + EPSB);
    float sc = rstd * g[f];
    scale[f] = sc;
    shift[f] = be[f] - mu * sc;
    float pv = p[f];
    red[f] = pv * pv;
    __syncthreads();
    for (int o = 64; o > 0; o >>= 1) {
        if (f < o) red[f] += red[f + o];
        __syncthreads();
    }
    if (f == 0) invp[0] = rsqrtf(red[0]);
}

__global__ void bn_relu_score_k(float* __restrict__ h, int M,
                                const float* __restrict__ scale, const float* __restrict__ shift,
                                const float* __restrict__ p, const float* __restrict__ invp,
                                float* __restrict__ score)
{
    int w = (blockIdx.x * blockDim.x + threadIdx.x) >> 5;
    int lane = threadIdx.x & 31;
    if (w >= M) return;
    float4* row = (float4*)(h + (size_t)w * HF);
    float4 v = row[lane];
    float4 sc = ((const float4*)scale)[lane];
    float4 sh = ((const float4*)shift)[lane];
    float4 pv = ((const float4*)p)[lane];
    v.x = fmaxf(v.x * sc.x + sh.x, 0.f);
    v.y = fmaxf(v.y * sc.y + sh.y, 0.f);
    v.z = fmaxf(v.z * sc.z + sh.z, 0.f);
    v.w = fmaxf(v.w * sc.w + sh.w, 0.f);
    row[lane] = v;
    float acc = v.x * pv.x + v.y * pv.y + v.z * pv.z + v.w * pv.w;
#pragma unroll
    for (int o = 16; o > 0; o >>= 1) acc += __shfl_xor_sync(0xffffffffu, acc, o);
    if (lane == 0) score[w] = acc * invp[0];
}

__global__ __launch_bounds__(1024) void topk_k(const float* __restrict__ score,
                                               int n, int k,
                                               int* __restrict__ map, int* __restrict__ perm)
{
    __shared__ float s[1024];
    __shared__ int id[1024];
    int g = blockIdx.x, t = threadIdx.x;
    s[t] = (t < n) ? score[g * n + t] : __int_as_float(0xff800000u);
    id[t] = t;
    __syncthreads();
    for (int size = 2; size <= 1024; size <<= 1) {
        for (int stride = size >> 1; stride > 0; stride >>= 1) {
            int pos = t ^ stride;
            if (pos > t) {
                bool desc = ((t & size) == 0);
                float s1 = s[t], s2 = s[pos];
                if (desc ? (s1 < s2) : (s1 > s2)) {
                    s[t] = s2; s[pos] = s1;
                    int tmp = id[t]; id[t] = id[pos]; id[pos] = tmp;
                }
            }
            __syncthreads();
        }
    }
    if (t < k) {
        int oldg = g * n + id[t];
        int newg = g * k + t;
        map[oldg] = newg;
        perm[newg] = oldg;
    }
}

__global__ void gather_gate_k(const float* __restrict__ h, const int* __restrict__ perm,
                              const float* __restrict__ score, float* __restrict__ out, int Mout)
{
    int w = (blockIdx.x * blockDim.x + threadIdx.x) >> 5;
    int lane = threadIdx.x & 31;
    if (w >= Mout) return;
    int old = perm[w];
    float gate = tanhf(score[old]);
    float4 v = ((const float4*)h)[(size_t)old * 32 + lane];
    v.x *= gate; v.y *= gate; v.z *= gate; v.w *= gate;
    ((float4*)out)[(size_t)w * 32 + lane] = v;
}

__global__ void readout_k(const float* __restrict__ hp, int k,
                          float* __restrict__ flat, int off)
{
    int g = blockIdx.x, f = threadIdx.x; // 128 threads
    const float* base = hp + ((size_t)g * k) * HF + f;
    float s = 0.f, m = __int_as_float(0xff800000u);
    for (int r = 0; r < k; r++) {
        float v = base[(size_t)r * HF];
        s += v;
        m = fmaxf(m, v);
    }
    flat[g * 1024 + off + f] = s;
    flat[g * 1024 + off + 128 + f] = m;
}

__global__ void remap_edges_k(int* __restrict__ src, int* __restrict__ dst,
                              const int* __restrict__ map)
{
    int e = blockIdx.x * blockDim.x + threadIdx.x;
    if (e >= E_TOT) return;
    int s = src[e];
    if (s < 0) return;
    int ns = map[s];
    int nd = map[dst[e]];
    if ((ns | nd) < 0) {
        src[e] = -1;
    } else {
        src[e] = ns;
        dst[e] = nd;
    }
}

// ---------------------------------------------------------------------------
// Final MLP
// ---------------------------------------------------------------------------
__global__ __launch_bounds__(512) void dense1_k(const float* __restrict__ flat,
                                                const float* __restrict__ Wd1,
                                                const float* __restrict__ bd1,
                                                float* __restrict__ hd)
{
    __shared__ float fr[1024];
    int g = blockIdx.x, t = threadIdx.x;
    fr[t] = flat[g * 1024 + t];
    fr[t + 512] = flat[g * 1024 + t + 512];
    __syncthreads();
    float acc = bd1[t];
    for (int kk = 0; kk < 1024; kk++)
        acc += fr[kk] * Wd1[(size_t)kk * 512 + t];
    hd[g * 512 + t] = fmaxf(acc, 0.f);
}

__global__ __launch_bounds__(512) void dense2_k(const float* __restrict__ hd,
                                                const float* __restrict__ Wd2,
                                                const float* __restrict__ bd2,
                                                float* __restrict__ out)
{
    __shared__ float hr[512];
    int g = blockIdx.x, t = threadIdx.x;
    hr[t] = hd[g * 512 + t];
    __syncthreads();
    if (t < 320) {
        int c = t >> 5, lane = t & 31;
        float acc = 0.f;
        for (int kk = lane; kk < 512; kk += 32)
            acc += hr[kk] * Wd2[(size_t)kk * 10 + c];
#pragma unroll
        for (int o = 16; o > 0; o >>= 1) acc += __shfl_down_sync(0xffffffffu, acc, o);
        if (lane == 0) out[g * 10 + c] = acc + bd2[c];
    }
}

// ---------------------------------------------------------------------------
// Host driver
// ---------------------------------------------------------------------------
extern "C" void kernel_launch(void* const* d_in, const int* in_sizes, int n_in,
                              void* d_out, int out_size)
{
    (void)in_sizes; (void)n_in; (void)out_size;

    const float* x  = (const float*)d_in[0];
    const int*   ei = (const int*)d_in[1];
    const float *Wl[4], *Wr[4], *bb[4], *gg[4], *be[4], *pp[4];
    for (int l = 0; l < 4; l++) {
        int b = 3 + 6 * l;
        Wl[l] = (const float*)d_in[b + 0];
        Wr[l] = (const float*)d_in[b + 1];
        bb[l] = (const float*)d_in[b + 2];
        gg[l] = (const float*)d_in[b + 3];
        be[l] = (const float*)d_in[b + 4];
        pp[l] = (const float*)d_in[b + 5];
    }
    const float* Wd1 = (const float*)d_in[27];
    const float* bd1 = (const float*)d_in[28];
    const float* Wd2 = (const float*)d_in[29];
    const float* bd2 = (const float*)d_in[30];
    float* out = (float*)d_out;

    float *h0, *h1, *agg, *cnt, *score, *colsum, *colsq, *scale, *shift, *invp, *flat, *hd;
    int *src, *dst, *perm, *map;
    cudaGetSymbolAddress((void**)&h0, g_h0);
    cudaGetSymbolAddress((void**)&h1, g_h1);
    cudaGetSymbolAddress((void**)&agg, g_agg);
    cudaGetSymbolAddress((void**)&cnt, g_cnt);
    cudaGetSymbolAddress((void**)&score, g_score);
    cudaGetSymbolAddress((void**)&colsum, g_colsum);
    cudaGetSymbolAddress((void**)&colsq, g_colsq);
    cudaGetSymbolAddress((void**)&scale, g_scale);
    cudaGetSymbolAddress((void**)&shift, g_shift);
    cudaGetSymbolAddress((void**)&invp, g_invp);
    cudaGetSymbolAddress((void**)&flat, g_flat);
    cudaGetSymbolAddress((void**)&hd, g_hd);
    cudaGetSymbolAddress((void**)&src, g_src);
    cudaGetSymbolAddress((void**)&dst, g_dst);
    cudaGetSymbolAddress((void**)&perm, g_perm);
    cudaGetSymbolAddress((void**)&map, g_map);

    init_edges_k<<<E_TOT / 256, 256>>>(ei, src, dst);

    const int ntin_a[4] = {32768, 26240, 20992, 16800};
    const int n_a[4]    = {1024, 820, 656, 525};
    const int k_a[4]    = {820, 656, 525, 420};

    const float* hin = x;
    for (int l = 0; l < 4; l++) {
        int M = ntin_a[l];
        int n = n_a[l];
        int kk = k_a[l];
        int Mout = GQ * kk;

        cudaMemsetAsync(agg, 0, (size_t)M * HF * sizeof(float));
        cudaMemsetAsync(cnt, 0, (size_t)M * sizeof(float));
        cudaMemsetAsync(colsum, 0, HF * sizeof(float));
        cudaMemsetAsync(colsq, 0, HF * sizeof(float));

        scatter_agg_k<<<E_TOT / 8, 256>>>(hin, src, dst, agg, cnt);
        mean_div_k<<<(M * 32 + 255) / 256, 256>>>(agg, cnt, M * 32);
        gemm_dual_k<<<(M + 127) / 128, 256>>>(agg, hin, Wl[l], Wr[l], bb[l], h1, M);
        bn_partial_k<<<(M + 255) / 256, 128>>>(h1, M, colsum, colsq);
        bn_finalize_k<<<1, 128>>>(colsum, colsq, 1.0f / (float)M,
                                  gg[l], be[l], pp[l], scale, shift, invp);
        bn_relu_score_k<<<(M + 7) / 8, 256>>>(h1, M, scale, shift, pp[l], invp, score);

        cudaMemsetAsync(map, 0xFF, (size_t)M * sizeof(int));
        topk_k<<<GQ, 1024>>>(score, n, kk, map, perm);
        gather_gate_k<<<(Mout + 7) / 8, 256>>>(h1, perm, score, h0, Mout);
        readout_k<<<GQ, 128>>>(h0, kk, flat, l * 256);
        if (l < 3) remap_edges_k<<<E_TOT / 256, 256>>>(src, dst, map);

        hin = h0;
    }

    dense1_k<<<GQ, 512>>>(flat, Wd1, bd1, hd);
    dense2_k<<<GQ, 512>>>(hd, Wd2, bd2, out);
}

// round 7
// speedup vs baseline: 1.3762x; 1.1519x over previous
#include <cuda_runtime.h>
#include <cuda_bf16.h>
#include <math.h>
#include <stdint.h>

// ---------------------------------------------------------------------------
// Problem constants
// ---------------------------------------------------------------------------
#define GQ      32
#define NT_MAX  32768
#define E_TOT   524288
#define HF      128
#define EPSB    1e-5f

// per-layer: ntin {32768,26240,20992,16800}  n {1024,820,656,525}  k {820,656,525,420}

// ---------------------------------------------------------------------------
// Device scratch
// ---------------------------------------------------------------------------
__device__ float g_h0[NT_MAX * HF];
__device__ float g_h1[NT_MAX * HF];
__device__ float g_agg[NT_MAX * HF];
__device__ float g_cnt[NT_MAX];
__device__ float g_score[NT_MAX];
__device__ int   g_perm[NT_MAX];
__device__ int   g_map[NT_MAX];
__device__ int   g_src[E_TOT];
__device__ int   g_dst[E_TOT];
__device__ float g_colsum[HF];
__device__ float g_colsq[HF];
__device__ float g_scale[HF];
__device__ float g_shift[HF];
__device__ float g_invp[1];
__device__ float g_flat[GQ * 1024];
__device__ float g_hd[GQ * 512];
// pre-split bf16 weight images, TRANSPOSED [n][k] as u32 pairs: [layer][half][128*64]
__device__ uint32_t g_wh[4][2][8192];
__device__ uint32_t g_wl[4][2][8192];

// ---------------------------------------------------------------------------
// Helpers
// ---------------------------------------------------------------------------
__device__ __forceinline__ uint32_t smem_u32(const void* p)
{
    uint32_t a;
    asm("{ .reg .u64 t; cvta.to.shared.u64 t, %1; cvt.u32.u64 %0, t; }"
        : "=r"(a) : "l"(p));
    return a;
}

__device__ __forceinline__ void red_add_v4(float* addr, float4 v)
{
    asm volatile("red.global.add.v4.f32 [%0], {%1,%2,%3,%4};"
                 :: "l"(addr), "f"(v.x), "f"(v.y), "f"(v.z), "f"(v.w)
                 : "memory");
}

__device__ __forceinline__ void split2(float f0, float f1, uint32_t& hi, uint32_t& lo)
{
    __nv_bfloat16 h0 = __float2bfloat16_rn(f0);
    __nv_bfloat16 h1 = __float2bfloat16_rn(f1);
    __nv_bfloat16 l0 = __float2bfloat16_rn(f0 - __bfloat162float(h0));
    __nv_bfloat16 l1 = __float2bfloat16_rn(f1 - __bfloat162float(h1));
    hi = (uint32_t)__bfloat16_as_ushort(h0) | ((uint32_t)__bfloat16_as_ushort(h1) << 16);
    lo = (uint32_t)__bfloat16_as_ushort(l0) | ((uint32_t)__bfloat16_as_ushort(l1) << 16);
}

// non-trans ldmatrix x4: reg j = 8x8 matrix j; lane L holds (row=L>>2, col=(L&3)*2)
__device__ __forceinline__ void ldmx4(uint32_t* r, uint32_t addr)
{
    asm volatile("ldmatrix.sync.aligned.m8n8.x4.shared.b16 {%0,%1,%2,%3}, [%4];"
                 : "=r"(r[0]), "=r"(r[1]), "=r"(r[2]), "=r"(r[3]) : "r"(addr));
}

__device__ __forceinline__ void mma16816(float* d, const uint32_t* a, const uint32_t* b)
{
    asm volatile("mma.sync.aligned.m16n8k16.row.col.f32.bf16.bf16.f32 "
                 "{%0,%1,%2,%3}, {%4,%5,%6,%7}, {%8,%9}, {%0,%1,%2,%3};"
                 : "+f"(d[0]), "+f"(d[1]), "+f"(d[2]), "+f"(d[3])
                 : "r"(a[0]), "r"(a[1]), "r"(a[2]), "r"(a[3]), "r"(b[0]), "r"(b[1]));
}

// ---------------------------------------------------------------------------
// Edge init / scatter aggregation (proven R3)
// ---------------------------------------------------------------------------
__global__ void init_edges_k(const int* __restrict__ ei,
                             int* __restrict__ src, int* __restrict__ dst)
{
    int e = blockIdx.x * blockDim.x + threadIdx.x;
    if (e >= E_TOT) return;
    src[e] = ei[e];
    dst[e] = ei[E_TOT + e];
}

__global__ void scatter_agg_k(const float* __restrict__ h,
                              const int* __restrict__ src, const int* __restrict__ dst,
                              float* __restrict__ agg, float* __restrict__ cnt)
{
    int w = (blockIdx.x * blockDim.x + threadIdx.x) >> 5;
    int lane = threadIdx.x & 31;
    if (w >= E_TOT) return;
    int s = __ldg(src + w);
    if (s < 0) return;
    int d = __ldg(dst + w);
    float4 v = __ldg(((const float4*)h) + (size_t)s * 32 + lane);
    red_add_v4(agg + (size_t)d * HF + lane * 4, v);
    if (lane == 0) atomicAdd(cnt + d, 1.0f);
}

// ---------------------------------------------------------------------------
// Weight prep: split into bf16 hi/lo, stored TRANSPOSED [n][k] as u32 k-pairs
// ---------------------------------------------------------------------------
__global__ void prep_w_k(const float* __restrict__ w0, const float* __restrict__ w1,
                         const float* __restrict__ w2, const float* __restrict__ w3,
                         const float* __restrict__ w4, const float* __restrict__ w5,
                         const float* __restrict__ w6, const float* __restrict__ w7)
{
    const float* W[8] = {w0, w1, w2, w3, w4, w5, w6, w7};
    int tid = blockIdx.x * blockDim.x + threadIdx.x;   // 65536 total
    int k2 = tid & 63;                  // k pair index
    int n  = (tid >> 6) & 127;
    int half = (tid >> 13) & 1;
    int layer = tid >> 14;
    const float* Wm = W[layer * 2 + half];
    int k = k2 * 2;
    float f0 = __ldg(Wm + (size_t)k * 128 + n);
    float f1 = __ldg(Wm + (size_t)(k + 1) * 128 + n);
    uint32_t hi, lo;
    split2(f0, f1, hi, lo);
    g_wh[layer][half][n * 64 + k2] = hi;
    g_wl[layer][half][n * 64 + k2] = lo;
}

// ---------------------------------------------------------------------------
// Tensor-core GEMM: h1[M,128] = (agg/cnt)@Wl + hin@Wr + bias
// fp32 accuracy via bf16 split (hi*hi + hi*lo + lo*hi).
// A fragments: registers (direct global loads + convert). B: static smem,
// [n][k] chunk of 64 k, non-trans ldmatrix. 8 warps = 4m x 2n, warp 32x64.
// ---------------------------------------------------------------------------
#define BROW 72   // u16 per B smem row: 64 bf16 data + 8 pad; 144 B, 16B-aligned

__global__ __launch_bounds__(256)
void gemm_mma_k(const float* __restrict__ Aagg, const float* __restrict__ Ain,
                const float* __restrict__ cnt, int layer,
                const float* __restrict__ bias, float* __restrict__ C, int M)
{
    __shared__ __align__(16) uint16_t Bh[128 * BROW];
    __shared__ __align__(16) uint16_t Bl[128 * BROW];

    const int tid = threadIdx.x;
    const int wid = tid >> 5, lane = tid & 31;
    const int wm = wid & 3, wn = wid >> 2;
    const int row0 = blockIdx.x * 128;
    const int gID = lane >> 2, tID = lane & 3;

    float acc[2][8][4];
#pragma unroll
    for (int mt = 0; mt < 2; mt++)
#pragma unroll
        for (int nt = 0; nt < 8; nt++)
#pragma unroll
            for (int c = 0; c < 4; c++) acc[mt][nt][c] = 0.f;

    // per-thread A rows + stage-0 mean scales
    int ra[2];
    float rc0[2][2];
#pragma unroll
    for (int mt = 0; mt < 2; mt++) {
        ra[mt] = row0 + wm * 32 + mt * 16 + gID;
        rc0[mt][0] = (ra[mt] < M) ? 1.0f / fmaxf(__ldg(cnt + ra[mt]), 1.0f) : 0.f;
        rc0[mt][1] = (ra[mt] + 8 < M) ? 1.0f / fmaxf(__ldg(cnt + ra[mt] + 8), 1.0f) : 0.f;
    }

    const uint32_t sbh = smem_u32(Bh), sbl = smem_u32(Bl);
    // non-trans ldmatrix lane addressing: matrix q = lane>>3, row r = lane&7
    const int b_q = lane >> 3, b_r = lane & 7;
    const uint32_t b_lane_off = (uint32_t)(((b_q >> 1) * 8 + b_r) * (BROW * 2))
                              + (uint32_t)((b_q & 1) * 16);

#pragma unroll 1
    for (int c = 0; c < 4; c++) {
        const int half = c >> 1;
        const int kb2 = (c & 1) * 32;          // u32 col base in weight image
        const float* Asrc = half ? Ain : Aagg;

        // ---- stage B chunk: 128 n-rows x 32 u32 (64 bf16 k) ----
        {
            const uint4* gh = (const uint4*)&g_wh[layer][half][0];
            const uint4* gl = (const uint4*)&g_wl[layer][half][0];
#pragma unroll
            for (int i = 0; i < 4; i++) {
                int item = tid + i * 256;      // 0..1023
                int r = item >> 3, ch = item & 7;
                uint4 vh = __ldg(gh + r * 16 + (kb2 >> 2) + ch);
                uint4 vl = __ldg(gl + r * 16 + (kb2 >> 2) + ch);
                *(uint4*)(Bh + r * BROW + ch * 8) = vh;
                *(uint4*)(Bl + r * BROW + ch * 8) = vl;
            }
        }
        __syncthreads();

#pragma unroll
        for (int kt = 0; kt < 4; kt++) {
            const int kcol = kb2 * 2 + kt * 16 + tID * 2;
            // ---- A fragments from global, converted in registers ----
            uint32_t ahi[2][4], alo[2][4];
#pragma unroll
            for (int mt = 0; mt < 2; mt++) {
                float2 v00 = make_float2(0.f, 0.f), v10 = v00, v01 = v00, v11 = v00;
                if (ra[mt] < M) {
                    v00 = *(const float2*)(Asrc + (size_t)ra[mt] * 128 + kcol);
                    v01 = *(const float2*)(Asrc + (size_t)ra[mt] * 128 + kcol + 8);
                }
                if (ra[mt] + 8 < M) {
                    v10 = *(const float2*)(Asrc + (size_t)(ra[mt] + 8) * 128 + kcol);
                    v11 = *(const float2*)(Asrc + (size_t)(ra[mt] + 8) * 128 + kcol + 8);
                }
                if (half == 0) {
                    v00.x *= rc0[mt][0]; v00.y *= rc0[mt][0];
                    v01.x *= rc0[mt][0]; v01.y *= rc0[mt][0];
                    v10.x *= rc0[mt][1]; v10.y *= rc0[mt][1];
                    v11.x *= rc0[mt][1]; v11.y *= rc0[mt][1];
                }
                split2(v00.x, v00.y, ahi[mt][0], alo[mt][0]);
                split2(v10.x, v10.y, ahi[mt][1], alo[mt][1]);
                split2(v01.x, v01.y, ahi[mt][2], alo[mt][2]);
                split2(v11.x, v11.y, ahi[mt][3], alo[mt][3]);
            }
            // ---- B fragments + mma ----
#pragma unroll
            for (int np = 0; np < 4; np++) {
                int n0 = wn * 64 + np * 16;
                uint32_t ab = (uint32_t)(n0 * (BROW * 2)) + (uint32_t)(kt * 32) + b_lane_off;
                uint32_t bhi[4], blo[4];
                ldmx4(bhi, sbh + ab);
                ldmx4(blo, sbl + ab);
#pragma unroll
                for (int j = 0; j < 2; j++) {
#pragma unroll
                    for (int mt = 0; mt < 2; mt++) {
                        mma16816(acc[mt][np * 2 + j], ahi[mt], &bhi[j * 2]);
                        mma16816(acc[mt][np * 2 + j], ahi[mt], &blo[j * 2]);
                        mma16816(acc[mt][np * 2 + j], alo[mt], &bhi[j * 2]);
                    }
                }
            }
        }
        __syncthreads();
    }

    // ---- epilogue: add bias, store ----
    const int colb = tID * 2;
#pragma unroll
    for (int mt = 0; mt < 2; mt++) {
        int r_lo = ra[mt];
        int r_hi = ra[mt] + 8;
#pragma unroll
        for (int nt = 0; nt < 8; nt++) {
            int col = wn * 64 + nt * 8 + colb;
            float2 b = *(const float2*)(bias + col);
            if (r_lo < M) {
                float2 o0 = make_float2(acc[mt][nt][0] + b.x, acc[mt][nt][1] + b.y);
                *(float2*)(C + (size_t)r_lo * 128 + col) = o0;
            }
            if (r_hi < M) {
                float2 o1 = make_float2(acc[mt][nt][2] + b.x, acc[mt][nt][3] + b.y);
                *(float2*)(C + (size_t)r_hi * 128 + col) = o1;
            }
        }
    }
}

// ---------------------------------------------------------------------------
// BN / score / topk / pool  (unchanged from R3)
// ---------------------------------------------------------------------------
__global__ void bn_partial_k(const float* __restrict__ h, int M,
                             float* __restrict__ colsum, float* __restrict__ colsq)
{
    int f = threadIdx.x;
    int r0 = blockIdx.x * 256;
    int r1 = min(r0 + 256, M);
    float s = 0.f, q = 0.f;
    for (int r = r0; r < r1; r++) {
        float v = h[(size_t)r * HF + f];
        s += v; q += v * v;
    }
    atomicAdd(&colsum[f], s);
    atomicAdd(&colsq[f], q);
}

__global__ void bn_finalize_k(const float* __restrict__ colsum, const float* __restrict__ colsq,
                              float invM,
                              const float* __restrict__ g, const float* __restrict__ be,
                              const float* __restrict__ p,
                              float* __restrict__ scale, float* __restrict__ shift,
                              float* __restrict__ invp)
{
    __shared__ float red[128];
    int f = threadIdx.x;
    float mu = colsum[f] * invM;
    float var = colsq[f] * invM - mu * mu;
    float rstd = rsqrtf(var + EPSB);
    float sc = rstd * g[f];
    scale[f] = sc;
    shift[f] = be[f] - mu * sc;
    float pv = p[f];
    red[f] = pv * pv;
    __syncthreads();
    for (int o = 64; o > 0; o >>= 1) {
        if (f < o) red[f] += red[f + o];
        __syncthreads();
    }
    if (f == 0) invp[0] = rsqrtf(red[0]);
}

__global__ void bn_relu_score_k(float* __restrict__ h, int M,
                                const float* __restrict__ scale, const float* __restrict__ shift,
                                const float* __restrict__ p, const float* __restrict__ invp,
                                float* __restrict__ score)
{
    int w = (blockIdx.x * blockDim.x + threadIdx.x) >> 5;
    int lane = threadIdx.x & 31;
    if (w >= M) return;
    float4* row = (float4*)(h + (size_t)w * HF);
    float4 v = row[lane];
    float4 sc = ((const float4*)scale)[lane];
    float4 sh = ((const float4*)shift)[lane];
    float4 pv = ((const float4*)p)[lane];
    v.x = fmaxf(v.x * sc.x + sh.x, 0.f);
    v.y = fmaxf(v.y * sc.y + sh.y, 0.f);
    v.z = fmaxf(v.z * sc.z + sh.z, 0.f);
    v.w = fmaxf(v.w * sc.w + sh.w, 0.f);
    row[lane] = v;
    float acc = v.x * pv.x + v.y * pv.y + v.z * pv.z + v.w * pv.w;
#pragma unroll
    for (int o = 16; o > 0; o >>= 1) acc += __shfl_xor_sync(0xffffffffu, acc, o);
    if (lane == 0) score[w] = acc * invp[0];
}

__global__ __launch_bounds__(1024) void topk_k(const float* __restrict__ score,
                                               int n, int k,
                                               int* __restrict__ map, int* __restrict__ perm)
{
    __shared__ float s[1024];
    __shared__ int id[1024];
    int g = blockIdx.x, t = threadIdx.x;
    s[t] = (t < n) ? score[g * n + t] : __int_as_float(0xff800000u);
    id[t] = t;
    __syncthreads();
    for (int size = 2; size <= 1024; size <<= 1) {
        for (int stride = size >> 1; stride > 0; stride >>= 1) {
            int pos = t ^ stride;
            if (pos > t) {
                bool desc = ((t & size) == 0);
                float s1 = s[t], s2 = s[pos];
                if (desc ? (s1 < s2) : (s1 > s2)) {
                    s[t] = s2; s[pos] = s1;
                    int tmp = id[t]; id[t] = id[pos]; id[pos] = tmp;
                }
            }
            __syncthreads();
        }
    }
    if (t < k) {
        int oldg = g * n + id[t];
        int newg = g * k + t;
        map[oldg] = newg;
        perm[newg] = oldg;
    }
}

__global__ void gather_gate_k(const float* __restrict__ h, const int* __restrict__ perm,
                              const float* __restrict__ score, float* __restrict__ out, int Mout)
{
    int w = (blockIdx.x * blockDim.x + threadIdx.x) >> 5;
    int lane = threadIdx.x & 31;
    if (w >= Mout) return;
    int old = perm[w];
    float gate = tanhf(score[old]);
    float4 v = ((const float4*)h)[(size_t)old * 32 + lane];
    v.x *= gate; v.y *= gate; v.z *= gate; v.w *= gate;
    ((float4*)out)[(size_t)w * 32 + lane] = v;
}

__global__ void readout_k(const float* __restrict__ hp, int k,
                          float* __restrict__ flat, int off)
{
    int g = blockIdx.x, f = threadIdx.x;
    const float* base = hp + ((size_t)g * k) * HF + f;
    float s = 0.f, m = __int_as_float(0xff800000u);
    for (int r = 0; r < k; r++) {
        float v = base[(size_t)r * HF];
        s += v;
        m = fmaxf(m, v);
    }
    flat[g * 1024 + off + f] = s;
    flat[g * 1024 + off + 128 + f] = m;
}

__global__ void remap_edges_k(int* __restrict__ src, int* __restrict__ dst,
                              const int* __restrict__ map)
{
    int e = blockIdx.x * blockDim.x + threadIdx.x;
    if (e >= E_TOT) return;
    int s = src[e];
    if (s < 0) return;
    int ns = map[s];
    int nd = map[dst[e]];
    if ((ns | nd) < 0) {
        src[e] = -1;
    } else {
        src[e] = ns;
        dst[e] = nd;
    }
}

// ---------------------------------------------------------------------------
// Final MLP
// ---------------------------------------------------------------------------
__global__ __launch_bounds__(512) void dense1_k(const float* __restrict__ flat,
                                                const float* __restrict__ Wd1,
                                                const float* __restrict__ bd1,
                                                float* __restrict__ hd)
{
    __shared__ float fr[1024];
    int g = blockIdx.x, t = threadIdx.x;
    fr[t] = flat[g * 1024 + t];
    fr[t + 512] = flat[g * 1024 + t + 512];
    __syncthreads();
    float acc = bd1[t];
    for (int kk = 0; kk < 1024; kk++)
        acc += fr[kk] * Wd1[(size_t)kk * 512 + t];
    hd[g * 512 + t] = fmaxf(acc, 0.f);
}

__global__ __launch_bounds__(512) void dense2_k(const float* __restrict__ hd,
                                                const float* __restrict__ Wd2,
                                                const float* __restrict__ bd2,
                                                float* __restrict__ out)
{
    __shared__ float hr[512];
    int g = blockIdx.x, t = threadIdx.x;
    hr[t] = hd[g * 512 + t];
    __syncthreads();
    if (t < 320) {
        int c = t >> 5, lane = t & 31;
        float acc = 0.f;
        for (int kk = lane; kk < 512; kk += 32)
            acc += hr[kk] * Wd2[(size_t)kk * 10 + c];
#pragma unroll
        for (int o = 16; o > 0; o >>= 1) acc += __shfl_down_sync(0xffffffffu, acc, o);
        if (lane == 0) out[g * 10 + c] = acc + bd2[c];
    }
}

// ---------------------------------------------------------------------------
// Host driver
// ---------------------------------------------------------------------------
extern "C" void kernel_launch(void* const* d_in, const int* in_sizes, int n_in,
                              void* d_out, int out_size)
{
    (void)in_sizes; (void)n_in; (void)out_size;

    const float* x  = (const float*)d_in[0];
    const int*   ei = (const int*)d_in[1];
    const float *Wl[4], *Wr[4], *bb[4], *gg[4], *be[4], *pp[4];
    for (int l = 0; l < 4; l++) {
        int b = 3 + 6 * l;
        Wl[l] = (const float*)d_in[b + 0];
        Wr[l] = (const float*)d_in[b + 1];
        bb[l] = (const float*)d_in[b + 2];
        gg[l] = (const float*)d_in[b + 3];
        be[l] = (const float*)d_in[b + 4];
        pp[l] = (const float*)d_in[b + 5];
    }
    const float* Wd1 = (const float*)d_in[27];
    const float* bd1 = (const float*)d_in[28];
    const float* Wd2 = (const float*)d_in[29];
    const float* bd2 = (const float*)d_in[30];
    float* out = (float*)d_out;

    float *h0, *h1, *agg, *cnt, *score, *colsum, *colsq, *scale, *shift, *invp, *flat, *hd;
    int *src, *dst, *perm, *map;
    cudaGetSymbolAddress((void**)&h0, g_h0);
    cudaGetSymbolAddress((void**)&h1, g_h1);
    cudaGetSymbolAddress((void**)&agg, g_agg);
    cudaGetSymbolAddress((void**)&cnt, g_cnt);
    cudaGetSymbolAddress((void**)&score, g_score);
    cudaGetSymbolAddress((void**)&colsum, g_colsum);
    cudaGetSymbolAddress((void**)&colsq, g_colsq);
    cudaGetSymbolAddress((void**)&scale, g_scale);
    cudaGetSymbolAddress((void**)&shift, g_shift);
    cudaGetSymbolAddress((void**)&invp, g_invp);
    cudaGetSymbolAddress((void**)&flat, g_flat);
    cudaGetSymbolAddress((void**)&hd, g_hd);
    cudaGetSymbolAddress((void**)&src, g_src);
    cudaGetSymbolAddress((void**)&dst, g_dst);
    cudaGetSymbolAddress((void**)&perm, g_perm);
    cudaGetSymbolAddress((void**)&map, g_map);

    init_edges_k<<<E_TOT / 256, 256>>>(ei, src, dst);
    prep_w_k<<<65536 / 256, 256>>>(Wl[0], Wr[0], Wl[1], Wr[1], Wl[2], Wr[2], Wl[3], Wr[3]);

    const int ntin_a[4] = {32768, 26240, 20992, 16800};
    const int n_a[4]    = {1024, 820, 656, 525};
    const int k_a[4]    = {820, 656, 525, 420};

    const float* hin = x;
    for (int l = 0; l < 4; l++) {
        int M = ntin_a[l];
        int n = n_a[l];
        int kk = k_a[l];
        int Mout = GQ * kk;

        cudaMemsetAsync(agg, 0, (size_t)M * HF * sizeof(float));
        cudaMemsetAsync(cnt, 0, (size_t)M * sizeof(float));
        cudaMemsetAsync(colsum, 0, HF * sizeof(float));
        cudaMemsetAsync(colsq, 0, HF * sizeof(float));

        scatter_agg_k<<<E_TOT / 8, 256>>>(hin, src, dst, agg, cnt);
        gemm_mma_k<<<(M + 127) / 128, 256>>>(agg, hin, cnt, l, bb[l], h1, M);
        bn_partial_k<<<(M + 255) / 256, 128>>>(h1, M, colsum, colsq);
        bn_finalize_k<<<1, 128>>>(colsum, colsq, 1.0f / (float)M,
                                  gg[l], be[l], pp[l], scale, shift, invp);
        bn_relu_score_k<<<(M + 7) / 8, 256>>>(h1, M, scale, shift, pp[l], invp, score);

        cudaMemsetAsync(map, 0xFF, (size_t)M * sizeof(int));
        topk_k<<<GQ, 1024>>>(score, n, kk, map, perm);
        gather_gate_k<<<(Mout + 7) / 8, 256>>>(h1, perm, score, h0, Mout);
        readout_k<<<GQ, 128>>>(h0, kk, flat, l * 256);
        if (l < 3) remap_edges_k<<<E_TOT / 256, 256>>>(src, dst, map);

        hin = h0;
    }

    dense1_k<<<GQ, 512>>>(flat, Wd1, bd1, hd);
    dense2_k<<<GQ, 512>>>(hd, Wd2, bd2, out);
}